// round 1
// baseline (speedup 1.0000x reference)
#include <cuda_runtime.h>

#define HID  128
#define NIN  64
#define NOUT 64
#define NB   256
#define NS   4096

typedef unsigned long long u64;

// Scratch for hidden states: [s][pair][j] packed float2 {row 2p, row 2p+1}. 512 MB.
__device__ u64 g_hs[NS][NB / 2][HID];

__device__ __forceinline__ u64 ffma2(u64 a, u64 b, u64 c) {
    u64 d;
    asm("fma.rn.f32x2 %0, %1, %2, %3;" : "=l"(d) : "l"(a), "l"(b), "l"(c));
    return d;
}
__device__ __forceinline__ u64 fadd2(u64 a, u64 b) {
    u64 d;
    asm("add.rn.f32x2 %0, %1, %2;" : "=l"(d) : "l"(a), "l"(b));
    return d;
}
__device__ __forceinline__ u64 pack2(float x, float y) {
    u64 d;
    asm("mov.b64 %0, {%1, %2};" : "=l"(d) : "f"(x), "f"(y));
    return d;
}
__device__ __forceinline__ float2 unpack2(u64 v) {
    float2 r;
    asm("mov.b64 {%0, %1}, %2;" : "=f"(r.x), "=f"(r.y) : "l"(v));
    return r;
}

// ---------------------------------------------------------------------------
// Kernel A: sequential recurrence, fused x-projection.
// Grid: 128 CTAs (one per batch row-pair), 256 threads.
// Thread (kh = tid>>7, j = tid&127) computes the k-half [kh*64, kh*64+64) of
// h_new[j] for BOTH rows of the pair, packed as f32x2. Wh/Wx column slices are
// register-resident, pre-duplicated {w,w}. h and x live in smem packed by row
// pair so inner-loop loads are pure broadcasts.
// ---------------------------------------------------------------------------
__global__ void __launch_bounds__(256, 1) rnn_recurrence(
    const float* __restrict__ x,  const float* __restrict__ Wh,
    const float* __restrict__ bh, const float* __restrict__ Wx,
    const float* __restrict__ bx)
{
    __shared__ __align__(16) u64 hbuf[2][HID];
    __shared__ __align__(16) u64 part[HID];
    __shared__ __align__(16) u64 xs[2][NIN];

    const int tid = threadIdx.x;
    const int j   = tid & 127;
    const int kh  = tid >> 7;     // k-half selector
    const int k0  = kh * 64;      // Wh k-range start
    const int i0  = kh * 32;      // Wx i-range start
    const int pr  = blockIdx.x;   // row pair
    const int b0  = pr * 2;

    // Register-resident, duplicated weight slices.
    u64 whd[64];
    u64 wxd[32];
#pragma unroll
    for (int i = 0; i < 64; i++) {
        float w = Wh[(k0 + i) * HID + j];
        whd[i] = pack2(w, w);
    }
#pragma unroll
    for (int i = 0; i < 32; i++) {
        float w = Wx[(i0 + i) * HID + j];
        wxd[i] = pack2(w, w);
    }
    u64 bias2 = 0;
    if (kh == 0) {
        float bsum = bh[j] + bx[j];   // fold both biases
        bias2 = pack2(bsum, bsum);
    }

    // x loader role (threads 0..127): rsel picks row of pair, ix the input idx.
    const int rsel = tid >> 6;
    const int ix   = tid & 63;
    const float* xrow = x + (long long)(b0 + rsel) * NS * NIN + ix;

    if (kh == 0) hbuf[0][j] = 0ull;   // h_{-1} = 0
    float xreg = 0.f;
    if (tid < 128) {
        ((float*)&xs[0][ix])[rsel] = xrow[0];     // x(s=0)
        xreg = xrow[1 * NIN];                      // x(s=1)
    }
    __syncthreads();

    for (int s = 0; s < NS; s++) {
        const int cur = s & 1, nxt = cur ^ 1;

        // Stage x(s+1) to smem, prefetch x(s+2) from gmem.
        if (tid < 128) {
            ((float*)&xs[nxt][ix])[rsel] = xreg;
            if (s + 2 < NS) xreg = xrow[(long long)(s + 2) * NIN];
        }

        // Main MACs: two accumulator chains to relax the RAW chain.
        u64 accA = bias2, accB = 0;
#pragma unroll
        for (int i = 0; i < 64; i += 2) {
            ulonglong2 hv = *(const ulonglong2*)&hbuf[cur][k0 + i];  // broadcast LDS.128
            accA = ffma2(whd[i],     hv.x, accA);
            accB = ffma2(whd[i + 1], hv.y, accB);
        }
#pragma unroll
        for (int i = 0; i < 32; i += 2) {
            ulonglong2 xv = *(const ulonglong2*)&xs[cur][i0 + i];    // broadcast LDS.128
            accA = ffma2(wxd[i],     xv.x, accA);
            accB = ffma2(wxd[i + 1], xv.y, accB);
        }
        u64 acc = fadd2(accA, accB);

        // split-k reduction + finalize
        if (kh) part[j] = acc;
        __syncthreads();
        if (!kh) {
            u64 tot = fadd2(acc, part[j]);
            float2 t = unpack2(tot);
            t.x = fmaxf(t.x, 0.f);
            t.y = fmaxf(t.y, 0.f);
            u64 h2 = pack2(t.x, t.y);
            hbuf[nxt][j] = h2;
            g_hs[s][pr][j] = h2;    // coalesced 1 KB STG per step per CTA
        }
        __syncthreads();
    }
}

// ---------------------------------------------------------------------------
// Kernel B: out[b][s][o] = hs[s][b][:] @ Wy + by.
// Grid: (NS/16 s-tiles, NB/4 pair-pairs), 256 threads.
// Thread (ph = tid>>7 pair-in-CTA, o = (tid&127)>>1, kh = tid&1 j-half).
// Wy column slice register-resident duplicated; j-half partials reduced via
// shfl.xor(1) inside the warp (no barriers in the s-loop).
// ---------------------------------------------------------------------------
__global__ void __launch_bounds__(256, 1) rnn_output(
    const float* __restrict__ Wy, const float* __restrict__ by,
    float* __restrict__ out)
{
    __shared__ __align__(16) u64 hst[2][16][HID];   // 32 KB

    const int tid = threadIdx.x;
    const int ph  = tid >> 7;
    const int o   = (tid & 127) >> 1;
    const int kh  = tid & 1;
    const int q   = blockIdx.y;          // pair-pair
    const int s0  = blockIdx.x * 16;

    u64 wyd[64];
#pragma unroll
    for (int i = 0; i < 64; i++) {
        float w = Wy[(kh * 64 + i) * NOUT + o];
        wyd[i] = pack2(w, w);
    }
    u64 by2 = 0;
    if (kh == 0) {
        float b = by[o];
        by2 = pack2(b, b);
    }

    // Cooperative tile load: 2 pairs x 16 steps x 128 j (u64) = 32 KB.
    for (int idx = tid; idx < 2 * 16 * HID / 2; idx += 256) {
        int idx2 = idx * 2;
        int jj   = idx2 & 127;
        int rest = idx2 >> 7;
        int si   = rest & 15;
        int php  = rest >> 4;
        *(ulonglong2*)&hst[php][si][jj] =
            *(const ulonglong2*)&g_hs[s0 + si][q * 2 + php][jj];
    }
    __syncthreads();

    const int p = q * 2 + ph;
#pragma unroll 2
    for (int si = 0; si < 16; si++) {
        u64 accA = by2, accB = 0;
#pragma unroll
        for (int i = 0; i < 64; i += 2) {
            ulonglong2 hv = *(const ulonglong2*)&hst[ph][si][kh * 64 + i];
            accA = ffma2(wyd[i],     hv.x, accA);
            accB = ffma2(wyd[i + 1], hv.y, accB);
        }
        float2 a = unpack2(fadd2(accA, accB));
        a.x += __shfl_xor_sync(0xffffffffu, a.x, 1);   // combine j-halves
        a.y += __shfl_xor_sync(0xffffffffu, a.y, 1);
        if (kh == 0) {
            int s = s0 + si;
            long long base = ((long long)(2 * p) * NS + s) * NOUT + o;
            out[base] = a.x;                                  // row 2p
            out[base + (long long)NS * NOUT] = a.y;           // row 2p+1
        }
    }
}

extern "C" void kernel_launch(void* const* d_in, const int* in_sizes, int n_in,
                              void* d_out, int out_size)
{
    const float* x  = (const float*)d_in[0];
    const float* Wh = (const float*)d_in[1];
    const float* bh = (const float*)d_in[2];
    const float* Wx = (const float*)d_in[3];
    const float* bx = (const float*)d_in[4];
    const float* Wy = (const float*)d_in[5];
    const float* by = (const float*)d_in[6];
    float* out = (float*)d_out;

    rnn_recurrence<<<NB / 2, 256>>>(x, Wh, bh, Wx, bx);
    rnn_output<<<dim3(NS / 16, NB / 4), 256>>>(Wy, by, out);
}